// round 5
// baseline (speedup 1.0000x reference)
#include <cuda_runtime.h>

// y = (W1*x > W0*x) ? +1 : -1, elementwise over 37.75M floats.
// HBM streaming roofline: 151MB read + 151MB write; 40.45us kernel = 7.47TB/s
// already (93% of spec). R5: reduce cross-CTA L1tex queue contention
// (spr model: oe*MLP_p1 >> Q_th at MLP=4) by dropping to MLP_p1=2 and doubling
// CTA parallelism: 128 thr/block * 2 float4/thread -> grid 36864 (exactly
// divisible for the benchmark shape: guard-free hot path).

__global__ void __launch_bounds__(128)
metaconv_sign2x128_kernel(const float4* __restrict__ x,
                          const float* __restrict__ W,
                          float4* __restrict__ out,
                          int n4) {
    const float w0 = W[0];
    const float w1 = W[1];

    const int base = blockIdx.x * (128 * 2) + threadIdx.x;
    const int i0 = base;
    const int i1 = base + 128;

    if (i1 < n4) {
        float4 v0 = __ldcs(&x[i0]);
        float4 v1 = __ldcs(&x[i1]);

        float4 r0, r1;
        r0.x = (w1 * v0.x > w0 * v0.x) ? 1.0f : -1.0f;
        r0.y = (w1 * v0.y > w0 * v0.y) ? 1.0f : -1.0f;
        r0.z = (w1 * v0.z > w0 * v0.z) ? 1.0f : -1.0f;
        r0.w = (w1 * v0.w > w0 * v0.w) ? 1.0f : -1.0f;
        r1.x = (w1 * v1.x > w0 * v1.x) ? 1.0f : -1.0f;
        r1.y = (w1 * v1.y > w0 * v1.y) ? 1.0f : -1.0f;
        r1.z = (w1 * v1.z > w0 * v1.z) ? 1.0f : -1.0f;
        r1.w = (w1 * v1.w > w0 * v1.w) ? 1.0f : -1.0f;

        __stcs(&out[i0], r0);
        __stcs(&out[i1], r1);
    } else {
        #pragma unroll
        for (int k = 0; k < 2; k++) {
            int i = base + k * 128;
            if (i < n4) {
                float4 v = __ldcs(&x[i]);
                float4 r;
                r.x = (w1 * v.x > w0 * v.x) ? 1.0f : -1.0f;
                r.y = (w1 * v.y > w0 * v.y) ? 1.0f : -1.0f;
                r.z = (w1 * v.z > w0 * v.z) ? 1.0f : -1.0f;
                r.w = (w1 * v.w > w0 * v.w) ? 1.0f : -1.0f;
                __stcs(&out[i], r);
            }
        }
    }
}

// Scalar tail kernel in case N % 4 != 0 (not needed for this shape, but safe).
__global__ void metaconv_sign_tail(const float* __restrict__ x,
                                   const float* __restrict__ W,
                                   float* __restrict__ out,
                                   int start, int n) {
    const float w0 = W[0];
    const float w1 = W[1];
    int i = start + blockIdx.x * blockDim.x + threadIdx.x;
    if (i < n) {
        float v = x[i];
        out[i] = (w1 * v > w0 * v) ? 1.0f : -1.0f;
    }
}

extern "C" void kernel_launch(void* const* d_in, const int* in_sizes, int n_in,
                              void* d_out, int out_size) {
    const float* x = (const float*)d_in[0];
    const float* W = (const float*)d_in[1];
    float* out = (float*)d_out;

    const int n = in_sizes[0];
    const int n4 = n >> 2;

    if (n4 > 0) {
        const int threads = 128;
        const int per_block = threads * 2;  // float4s per block
        int blocks = (n4 + per_block - 1) / per_block;
        metaconv_sign2x128_kernel<<<blocks, threads>>>(
            (const float4*)x, W, (float4*)out, n4);
    }
    const int rem = n - (n4 << 2);
    if (rem > 0) {
        metaconv_sign_tail<<<1, 32>>>(x, W, out, n4 << 2, n);
    }
}

// round 6
// speedup vs baseline: 1.0033x; 1.0033x over previous
#include <cuda_runtime.h>

// FINAL (= R4 optimum): y = (W1*x > W0*x) ? +1 : -1 elementwise over
// 37.75M floats. Pure HBM streaming, 151MB read + 151MB write.
// Achieves 7.47 TB/s (93% of 8TB/s spec) — memory-roofline bound.
//
// Config sweep results (kernel time / DRAM busy):
//   256thr x MLP1-2: 42.4us/75.6%   256thr x MLP4: 40.8us/76.4%
//   512thr x MLP8:   42.0us/74.0%   128thr x MLP2: 41.8us/74.6%
//   128thr x MLP4:   40.45us/77.5%  <== optimum (this kernel)
//
// 128 threads/block, 4 front-batched float4 loads/thread, streaming cache
// hints (zero reuse). Grid = 18432 for the benchmark shape (exactly
// divisible -> guard-free hot path); edge/tail paths kept for shape safety.

__global__ void __launch_bounds__(128)
metaconv_sign4x128_kernel(const float4* __restrict__ x,
                          const float* __restrict__ W,
                          float4* __restrict__ out,
                          int n4) {
    const float w0 = W[0];
    const float w1 = W[1];

    const int base = blockIdx.x * (128 * 4) + threadIdx.x;
    const int i0 = base;
    const int i1 = base + 128;
    const int i2 = base + 256;
    const int i3 = base + 384;

    if (i3 < n4) {
        float4 v0 = __ldcs(&x[i0]);
        float4 v1 = __ldcs(&x[i1]);
        float4 v2 = __ldcs(&x[i2]);
        float4 v3 = __ldcs(&x[i3]);

        float4 r0, r1, r2, r3;
        r0.x = (w1 * v0.x > w0 * v0.x) ? 1.0f : -1.0f;
        r0.y = (w1 * v0.y > w0 * v0.y) ? 1.0f : -1.0f;
        r0.z = (w1 * v0.z > w0 * v0.z) ? 1.0f : -1.0f;
        r0.w = (w1 * v0.w > w0 * v0.w) ? 1.0f : -1.0f;
        r1.x = (w1 * v1.x > w0 * v1.x) ? 1.0f : -1.0f;
        r1.y = (w1 * v1.y > w0 * v1.y) ? 1.0f : -1.0f;
        r1.z = (w1 * v1.z > w0 * v1.z) ? 1.0f : -1.0f;
        r1.w = (w1 * v1.w > w0 * v1.w) ? 1.0f : -1.0f;
        r2.x = (w1 * v2.x > w0 * v2.x) ? 1.0f : -1.0f;
        r2.y = (w1 * v2.y > w0 * v2.y) ? 1.0f : -1.0f;
        r2.z = (w1 * v2.z > w0 * v2.z) ? 1.0f : -1.0f;
        r2.w = (w1 * v2.w > w0 * v2.w) ? 1.0f : -1.0f;
        r3.x = (w1 * v3.x > w0 * v3.x) ? 1.0f : -1.0f;
        r3.y = (w1 * v3.y > w0 * v3.y) ? 1.0f : -1.0f;
        r3.z = (w1 * v3.z > w0 * v3.z) ? 1.0f : -1.0f;
        r3.w = (w1 * v3.w > w0 * v3.w) ? 1.0f : -1.0f;

        __stcs(&out[i0], r0);
        __stcs(&out[i1], r1);
        __stcs(&out[i2], r2);
        __stcs(&out[i3], r3);
    } else {
        #pragma unroll
        for (int k = 0; k < 4; k++) {
            int i = base + k * 128;
            if (i < n4) {
                float4 v = __ldcs(&x[i]);
                float4 r;
                r.x = (w1 * v.x > w0 * v.x) ? 1.0f : -1.0f;
                r.y = (w1 * v.y > w0 * v.y) ? 1.0f : -1.0f;
                r.z = (w1 * v.z > w0 * v.z) ? 1.0f : -1.0f;
                r.w = (w1 * v.w > w0 * v.w) ? 1.0f : -1.0f;
                __stcs(&out[i], r);
            }
        }
    }
}

// Scalar tail kernel in case N % 4 != 0 (not needed for this shape, but safe).
__global__ void metaconv_sign_tail(const float* __restrict__ x,
                                   const float* __restrict__ W,
                                   float* __restrict__ out,
                                   int start, int n) {
    const float w0 = W[0];
    const float w1 = W[1];
    int i = start + blockIdx.x * blockDim.x + threadIdx.x;
    if (i < n) {
        float v = x[i];
        out[i] = (w1 * v > w0 * v) ? 1.0f : -1.0f;
    }
}

extern "C" void kernel_launch(void* const* d_in, const int* in_sizes, int n_in,
                              void* d_out, int out_size) {
    const float* x = (const float*)d_in[0];
    const float* W = (const float*)d_in[1];
    float* out = (float*)d_out;

    const int n = in_sizes[0];
    const int n4 = n >> 2;

    if (n4 > 0) {
        const int threads = 128;
        const int per_block = threads * 4;  // float4s per block
        int blocks = (n4 + per_block - 1) / per_block;
        metaconv_sign4x128_kernel<<<blocks, threads>>>(
            (const float4*)x, W, (float4*)out, n4);
    }
    const int rem = n - (n4 << 2);
    if (rem > 0) {
        metaconv_sign_tail<<<1, 32>>>(x, W, out, n4 << 2, n);
    }
}